// round 16
// baseline (speedup 1.0000x reference)
#include <cuda_runtime.h>
#include <float.h>

#define Tn   2048
#define Bn   512
#define INn  27
#define Hn   64
#define OUTn 26
#define Gn   256   // 4*H
#define BPC  4     // batches per CTA in stage 1

// scratch: h history only (256 MB). The xw precompute kernel + 1 GiB scratch
// are GONE -- x.W_ih is now computed inside the lstm loop's idle issue slots.
__device__ float g_hall[Tn * Bn * Hn];

// ---- packed f32x2 helpers (Blackwell FFMA2) ----
__device__ __forceinline__ unsigned long long pack2(float lo, float hi) {
    unsigned long long r;
    asm("mov.b64 %0, {%1, %2};" : "=l"(r) : "f"(lo), "f"(hi));
    return r;
}
__device__ __forceinline__ void unpack2(unsigned long long v, float& lo, float& hi) {
    asm("mov.b64 {%0, %1}, %2;" : "=f"(lo), "=f"(hi) : "l"(v));
}
__device__ __forceinline__ unsigned long long ffma2(unsigned long long a,
                                                    unsigned long long b,
                                                    unsigned long long c) {
    unsigned long long d;
    asm("fma.rn.f32x2 %0, %1, %2, %3;" : "=l"(d) : "l"(a), "l"(b), "l"(c));
    return d;
}
__device__ __forceinline__ float ex2f(float x) {
    float y; asm("ex2.approx.f32 %0, %1;" : "=f"(y) : "f"(x)); return y;
}
__device__ __forceinline__ float rcpf(float x) {
    float y; asm("rcp.approx.f32 %0, %1;" : "=f"(y) : "f"(x)); return y;
}

// ============================================================================
// Fused LSTM: 512 LSTMs, 4 batches/CTA, grid 128 (single wave, <=1 CTA/SM),
// 512 threads; thread = 1 gate x 2 batches; W_hh AND W_ih register-resident.
//
// Pipeline per step t (one barrier, as before):
//   - 108 threads LDG x[t+2] (1 float each) -> register
//   - gate pre-acts from h (64 FFMA2) + xr (computed LAST step)
//   - activations (MUFU) + shfl gather
//   - xw[t+1] = x_s[t&1] . W_ih + bias  (28 FFMA2 + 14 broadcast LDS.128)
//       <- fills the MUFU/shfl latency window that profiling shows is idle
//   - STS x[t+2] into x_s[(t+1)&1]
//   - cell/hidden update, h_s + g_hall stores, barrier; xr <- xwn
// Invariant: at step t, x_s[t&1] holds x[t+1].
// ============================================================================
__global__ __launch_bounds__(512, 1)
void lstm_kernel(const float* __restrict__ x,      // [T,B,IN]
                 const float* __restrict__ W_ih,   // [256,27]
                 const float* __restrict__ W_hh,   // [256,64]
                 const float* __restrict__ b_ih,
                 const float* __restrict__ b_hh)
{
    const int tid  = threadIdx.x;
    const int lane = tid & 31;
    const int warp = tid >> 5;
    const int pair = warp >> 3;               // 0 or 1
    const int hg   = warp & 7;
    const int hloc = hg * 8 + (lane & 7);
    const int gtyp = lane >> 3;               // 0:i 1:f 2:g 3:o
    const int g    = gtyp * 64 + hloc;

    const int bl0 = 2 * pair;
    const int bg0 = blockIdx.x * BPC + bl0;

    __shared__ __align__(16) float h_s[2][BPC][Hn];
    __shared__ __align__(16) float x_s[2][BPC][28];   // 28th col = 0 pad

    // ---- weights -> registers (f32x2 packed) ----
    unsigned long long whh[32];
    unsigned long long wih[14];
    {
        const float* wr = W_hh + g * Hn;
#pragma unroll
        for (int k = 0; k < 32; k++) whh[k] = pack2(wr[2 * k], wr[2 * k + 1]);
        const float* wr2 = W_ih + g * INn;
#pragma unroll
        for (int j = 0; j < 13; j++) wih[j] = pack2(wr2[2 * j], wr2[2 * j + 1]);
        wih[13] = pack2(wr2[26], 0.0f);
    }
    const float bias = b_ih[g] + b_hh[g];

    // act = A * rcp(1 + ex2(K*pre)) + C   (gtyp2: tanh = 2*sigm(2x)-1)
    const float K = (gtyp == 2) ? -2.8853900817779268f : -1.4426950408889634f;
    const float A = (gtyp == 2) ?  2.0f : 1.0f;
    const float C = (gtyp == 2) ? -1.0f : 0.0f;

    float c = 0.0f;

    // x staging duty: 108 threads, one (batch, col) each
    const bool do_x = tid < BPC * INn;
    const int  xb   = tid / INn;
    const int  xi   = tid - xb * INn;
    const int  gbx  = blockIdx.x * BPC + xb;
    const float* xptr = x + ((size_t)2 * Bn + gbx) * INn + xi;   // t = 2

    const int bsel = (lane >> 3) & 1;
    float* hallp = g_hall + (size_t)(bg0 + bsel) * Hn + hloc;

    // ---- init smem ----
    if (tid < BPC * Hn) ((float*)h_s[0])[tid] = 0.0f;
    if (tid < 8) x_s[tid >> 2][tid & 3][27] = 0.0f;     // zero pad cols
    if (do_x) {
        x_s[1][xb][xi] = x[(size_t)gbx * INn + xi];                 // x[0]
        x_s[0][xb][xi] = x[((size_t)Bn + gbx) * INn + xi];          // x[1]
    }
    __syncthreads();

    // prologue: xr = xw[0] from x_s[1]
    float2 xr;
    {
        const ulonglong2* X0 = (const ulonglong2*)x_s[1][bl0];
        const ulonglong2* X1 = (const ulonglong2*)x_s[1][bl0 + 1];
        unsigned long long xa0 = 0ull, xa1 = 0ull;
#pragma unroll
        for (int j = 0; j < 7; j++) {
            ulonglong2 u0 = X0[j], u1 = X1[j];
            xa0 = ffma2(u0.x, wih[2 * j],     xa0);
            xa0 = ffma2(u0.y, wih[2 * j + 1], xa0);
            xa1 = ffma2(u1.x, wih[2 * j],     xa1);
            xa1 = ffma2(u1.y, wih[2 * j + 1], xa1);
        }
        float l0, h0, l1, h1;
        unpack2(xa0, l0, h0);
        unpack2(xa1, l1, h1);
        xr = make_float2(bias + (l0 + h0), bias + (l1 + h1));
    }
    __syncthreads();   // x_s[1] read done before step-0 overwrites it

    int buf = 0;
    for (int t = 0; t < Tn; t++) {
        // LDG x[t+2] (consumed by STS near end of this step)
        float xldg = 0.0f;
        if (do_x && (t + 2) < Tn) xldg = *xptr;
        xptr += (size_t)Bn * INn;

        // ---- gate pre-activation: h . W_hh (+xr, biases inside xr) ----
        unsigned long long a0 = 0ull, a1 = 0ull;
        const ulonglong2* hp0 = (const ulonglong2*)h_s[buf][bl0];
        const ulonglong2* hp1 = (const ulonglong2*)h_s[buf][bl0 + 1];
#pragma unroll
        for (int k = 0; k < 16; k++) {
            ulonglong2 h0 = hp0[k];
            ulonglong2 h1 = hp1[k];
            a0 = ffma2(h0.x, whh[2 * k],     a0);
            a0 = ffma2(h0.y, whh[2 * k + 1], a0);
            a1 = ffma2(h1.x, whh[2 * k],     a1);
            a1 = ffma2(h1.y, whh[2 * k + 1], a1);
        }
        float l0, u0, l1, u1;
        unpack2(a0, l0, u0);
        unpack2(a1, l1, u1);
        float acc0 = (xr.x + l0) + u0;
        float acc1 = (xr.y + l1) + u1;

        float act0 = fmaf(A, rcpf(1.0f + ex2f(K * acc0)), C);
        float act1 = fmaf(A, rcpf(1.0f + ex2f(K * acc1)), C);

        // shfl gather (issue now; results consumed after the xw block)
        const int base = lane & 7;
        float i0 = __shfl_sync(0xffffffffu, act0, base);
        float i1 = __shfl_sync(0xffffffffu, act1, base);
        float f0 = __shfl_sync(0xffffffffu, act0, base + 8);
        float f1 = __shfl_sync(0xffffffffu, act1, base + 8);
        float g0 = __shfl_sync(0xffffffffu, act0, base + 16);
        float g1 = __shfl_sync(0xffffffffu, act1, base + 16);
        float o0 = __shfl_sync(0xffffffffu, act0, base + 24);
        float o1 = __shfl_sync(0xffffffffu, act1, base + 24);

        // ---- xw[t+1] from x_s[t&1] (fills MUFU/shfl latency window) ----
        float2 xwn;
        {
            const ulonglong2* X0 = (const ulonglong2*)x_s[t & 1][bl0];
            const ulonglong2* X1 = (const ulonglong2*)x_s[t & 1][bl0 + 1];
            unsigned long long xa0 = 0ull, xa1 = 0ull;
#pragma unroll
            for (int j = 0; j < 7; j++) {
                ulonglong2 u0 = X0[j], u1 = X1[j];
                xa0 = ffma2(u0.x, wih[2 * j],     xa0);
                xa0 = ffma2(u0.y, wih[2 * j + 1], xa0);
                xa1 = ffma2(u1.x, wih[2 * j],     xa1);
                xa1 = ffma2(u1.y, wih[2 * j + 1], xa1);
            }
            float xl0, xh0, xl1, xh1;
            unpack2(xa0, xl0, xh0);
            unpack2(xa1, xl1, xh1);
            xwn = make_float2(bias + (xl0 + xh0), bias + (xl1 + xh1));
        }

        // stage x[t+2] for next step's xw compute
        if (do_x) x_s[(t + 1) & 1][xb][xi] = xldg;

        // ---- cell/hidden update: lanes 0-15 own (h = hloc, b = bl0+bsel) ----
        const bool sel = (lane & 8) != 0;
        float iv = sel ? i1 : i0;
        float fv = sel ? f1 : f0;
        float gv = sel ? g1 : g0;
        float ov = sel ? o1 : o0;
        c = fmaf(fv, c, iv * gv);
        float th = fmaf(2.0f, rcpf(1.0f + ex2f(-2.8853900817779268f * c)), -1.0f);
        float hv = ov * th;
        if (lane < 16) {
            h_s[buf ^ 1][bl0 + bsel][hloc] = hv;
            *hallp = hv;
        }
        hallp += (size_t)Bn * Hn;
        __syncthreads();
        buf ^= 1;
        xr = xwn;
    }
}

// ============================================================================
// Stage 2 (unchanged, ~71us reproducible): single-pass BN-stats +
// masked-extrema + pool + FC, one CTA per timestep.
// ============================================================================
__global__ __launch_bounds__(256)
void bn_pool_fc_kernel(const float* __restrict__ pg,     // [T,OUT]
                       const float* __restrict__ gamma,  // [H]
                       const float* __restrict__ beta,   // [H]
                       const float* __restrict__ W_fc,   // [OUT, H+OUT]
                       const float* __restrict__ b_fc,   // [OUT]
                       const float* __restrict__ mask,   // [B,H]
                       float* __restrict__ out)          // [T,1,OUT]
{
    const int t   = blockIdx.x;
    const int tid = threadIdx.x;
    const int h   = tid & 63;
    const int grp = tid >> 6;

    const float* base = g_hall + (size_t)t * Bn * Hn;

    __shared__ float rS[4][Hn], rQ[4][Hn], rMx[4][Hn], rMn[4][Hn],
                     rMv[4][Hn], rZ[4][Hn];
    __shared__ float pooled[Hn];

    float s = 0.0f, ss = 0.0f;
    float vmx = -FLT_MAX, vmn = FLT_MAX, mv = 0.0f, anyz = 0.0f;
#pragma unroll 4
    for (int bb = grp; bb < Bn; bb += 4) {
        float v = base[bb * Hn + h];
        float m = mask[bb * Hn + h];
        s  += v;
        ss += v * v;
        if (m > 0.0f) {
            vmx = fmaxf(vmx, v);
            vmn = fminf(vmn, v);
            mv  = fmaxf(mv, m);
        } else {
            anyz = 1.0f;
        }
    }
    rS[grp][h] = s;    rQ[grp][h] = ss;
    rMx[grp][h] = vmx; rMn[grp][h] = vmn;
    rMv[grp][h] = mv;  rZ[grp][h] = anyz;
    __syncthreads();

    if (tid < Hn) {
        float sum = rS[0][tid] + rS[1][tid] + rS[2][tid] + rS[3][tid];
        float sq  = rQ[0][tid] + rQ[1][tid] + rQ[2][tid] + rQ[3][tid];
        float mx  = fmaxf(fmaxf(rMx[0][tid], rMx[1][tid]),
                          fmaxf(rMx[2][tid], rMx[3][tid]));
        float mn  = fminf(fminf(rMn[0][tid], rMn[1][tid]),
                          fminf(rMn[2][tid], rMn[3][tid]));
        float m   = fmaxf(fmaxf(rMv[0][tid], rMv[1][tid]),
                          fmaxf(rMv[2][tid], rMv[3][tid]));
        float z   = fmaxf(fmaxf(rZ[0][tid], rZ[1][tid]),
                          fmaxf(rZ[2][tid], rZ[3][tid]));
        float mean = sum * (1.0f / Bn);
        float var  = sq * (1.0f / Bn) - mean * mean;
        float rstd = rsqrtf(var + 1e-5f);
        float sc   = rstd * gamma[tid];
        float sh   = beta[tid] - mean * sc;

        float p;
        if (mx == -FLT_MAX) {
            p = 0.0f;
        } else {
            float vstar = (sc >= 0.0f) ? mx : mn;
            p = m * (vstar * sc + sh);
            if (z > 0.0f) p = fmaxf(p, 0.0f);
        }
        pooled[tid] = p;
    }
    __syncthreads();

    if (tid < OUTn) {
        const float* w = W_fc + tid * (Hn + OUTn);
        float acc = b_fc[tid];
#pragma unroll
        for (int k = 0; k < Hn; k++) acc += pooled[k] * w[k];
#pragma unroll
        for (int k = 0; k < OUTn; k++) acc += pg[t * OUTn + k] * w[Hn + k];
        out[t * OUTn + tid] = acc;
    }
}

// ============================================================================
// Launch -- two kernels now (xw fused into lstm)
// ============================================================================
extern "C" void kernel_launch(void* const* d_in, const int* in_sizes, int n_in,
                              void* d_out, int out_size) {
    const float* x      = (const float*)d_in[0];
    const float* pg     = (const float*)d_in[1];
    const float* W_ih   = (const float*)d_in[2];
    const float* W_hh   = (const float*)d_in[3];
    const float* b_ih   = (const float*)d_in[4];
    const float* b_hh   = (const float*)d_in[5];
    const float* gamma  = (const float*)d_in[6];
    const float* beta   = (const float*)d_in[7];
    const float* W_fc   = (const float*)d_in[8];
    const float* b_fc   = (const float*)d_in[9];
    const float* dmask  = (const float*)d_in[10];
    float* out = (float*)d_out;

    lstm_kernel<<<Bn / BPC, 512>>>(x, W_ih, W_hh, b_ih, b_hh);
    bn_pool_fc_kernel<<<Tn, 256>>>(pg, gamma, beta, W_fc, b_fc, dmask, out);
}

// round 17
// speedup vs baseline: 1.2234x; 1.2234x over previous
#include <cuda_runtime.h>
#include <float.h>

#define Tn   2048
#define Bn   512
#define INn  27
#define Hn   64
#define OUTn 26
#define Gn   256   // 4*H
#define BPC  4     // batches per CTA in stage 1

// scratch: h history (256 MB) + input-gate preactivations (padded by TWO
// timesteps so the depth-2 lstm prefetch reads t=Tn, Tn+1 unconditionally;
// those values are dead). g_xw2[(t*(Bn/2)+bp)*Gn+g'] = {pre[2bp], pre[2bp+1]}
__device__ float  g_hall[Tn * Bn * Hn];
__device__ float2 g_xw2[(size_t)(Tn + 2) * (Bn / 2) * Gn];

// ---- packed f32x2 helpers (Blackwell FFMA2) ----
__device__ __forceinline__ unsigned long long pack2(float lo, float hi) {
    unsigned long long r;
    asm("mov.b64 %0, {%1, %2};" : "=l"(r) : "f"(lo), "f"(hi));
    return r;
}
__device__ __forceinline__ void unpack2(unsigned long long v, float& lo, float& hi) {
    asm("mov.b64 {%0, %1}, %2;" : "=f"(lo), "=f"(hi) : "l"(v));
}
__device__ __forceinline__ unsigned long long ffma2(unsigned long long a,
                                                    unsigned long long b,
                                                    unsigned long long c) {
    unsigned long long d;
    asm("fma.rn.f32x2 %0, %1, %2, %3;" : "=l"(d) : "l"(a), "l"(b), "l"(c));
    return d;
}
__device__ __forceinline__ unsigned long long add2(unsigned long long a,
                                                   unsigned long long b) {
    unsigned long long d;
    asm("add.rn.f32x2 %0, %1, %2;" : "=l"(d) : "l"(a), "l"(b));
    return d;
}
__device__ __forceinline__ float tanhf_fast(float x) {
    float y; asm("tanh.approx.f32 %0, %1;" : "=f"(y) : "f"(x)); return y;
}

// ============================================================================
// Kernel 0 (EXACT R11/R12/R15 code, 410us thrice-reproduced): two gates per
// thread, k-packed weights, each broadcast x LDS.128 feeds 4 accumulator
// streams.
// ============================================================================
__global__ __launch_bounds__(256)
void xw_kernel(const float* __restrict__ x,      // [T,B,IN]
               const float* __restrict__ W_ih,   // [256,27]
               const float* __restrict__ b_ih,
               const float* __restrict__ b_hh)
{
    const int t    = blockIdx.x;
    const int tid  = threadIdx.x;
    const int gidx = tid & 127;
    const int half = tid >> 7;          // pair-group within tile
    const int gpA  = gidx;              // permuted gate ids
    const int gpB  = gidx + 128;

    auto decode = [](int gp) {
        int hg = gp >> 5, rem = gp & 31;
        return (rem >> 3) * 64 + hg * 8 + (rem & 7);
    };
    const int gA = decode(gpA);
    const int gB = decode(gpB);

    unsigned long long wA[14], wB[14];
    {
        const float* ra = W_ih + gA * INn;
        const float* rb = W_ih + gB * INn;
#pragma unroll
        for (int j = 0; j < 13; j++) {
            wA[j] = pack2(ra[2 * j], ra[2 * j + 1]);
            wB[j] = pack2(rb[2 * j], rb[2 * j + 1]);
        }
        wA[13] = pack2(ra[26], 0.0f);
        wB[13] = pack2(rb[26], 0.0f);
    }
    const float biasA = b_ih[gA] + b_hh[gA];
    const float biasB = b_ih[gB] + b_hh[gB];

    __shared__ __align__(16) unsigned long long xs[32][14];

    float2* outb = g_xw2 + (size_t)t * (Bn / 2) * Gn;

    for (int tb = 0; tb < Bn; tb += 32) {
        __syncthreads();
        for (int idx = tid; idx < 32 * 14; idx += 256) {
            int r = idx / 14, j = idx - r * 14;
            const float* xrow = x + ((size_t)t * Bn + tb + r) * INn;
            float lo = xrow[2 * j];
            float hi = (j < 13) ? xrow[2 * j + 1] : 0.0f;
            xs[r][j] = pack2(lo, hi);
        }
        __syncthreads();
#pragma unroll
        for (int pl = 0; pl < 8; pl++) {
            int p  = half * 8 + pl;
            const ulonglong2* X0 = (const ulonglong2*)xs[2 * p];
            const ulonglong2* X1 = (const ulonglong2*)xs[2 * p + 1];
            unsigned long long a00 = 0ull, a01 = 0ull, a10 = 0ull, a11 = 0ull;
#pragma unroll
            for (int j2 = 0; j2 < 7; j2++) {
                ulonglong2 U0 = X0[j2];
                ulonglong2 U1 = X1[j2];
                a00 = ffma2(U0.x, wA[2 * j2],     a00);
                a00 = ffma2(U0.y, wA[2 * j2 + 1], a00);
                a01 = ffma2(U1.x, wA[2 * j2],     a01);
                a01 = ffma2(U1.y, wA[2 * j2 + 1], a01);
                a10 = ffma2(U0.x, wB[2 * j2],     a10);
                a10 = ffma2(U0.y, wB[2 * j2 + 1], a10);
                a11 = ffma2(U1.x, wB[2 * j2],     a11);
                a11 = ffma2(U1.y, wB[2 * j2 + 1], a11);
            }
            float l, h;
            unpack2(a00, l, h); float pA0 = biasA + (l + h);
            unpack2(a01, l, h); float pA1 = biasA + (l + h);
            unpack2(a10, l, h); float pB0 = biasB + (l + h);
            unpack2(a11, l, h); float pB1 = biasB + (l + h);
            size_t bp = (size_t)(tb >> 1) + p;
            outb[bp * Gn + gpA] = make_float2(pA0, pA1);
            outb[bp * Gn + gpB] = make_float2(pB0, pB1);
        }
    }
}

// ============================================================================
// Stage 1 (R15 base, best measured; v6: tanh.approx activations).
// 512 LSTMs, 4 batches/CTA, grid 128 (single wave, <=1 CTA/SM), 512 threads;
// thread = 1 gate x 2 batches; W_hh register-resident; depth-2 xw prefetch.
// Activations: sigmoid(x) = 0.5*tanh(0.5x)+0.5, tanh direct -- ONE MUFU each
// (was ex2->rcp serial chains): MUFU/thread 6 -> 3, act latency ~40 -> ~16 cyc
// on the critical path before the shfl gather and before the h store.
// ============================================================================
__global__ __launch_bounds__(512, 1)
void lstm_kernel(const float* __restrict__ W_hh)   // [256,64]
{
    const int tid  = threadIdx.x;
    const int lane = tid & 31;
    const int warp = tid >> 5;
    const int pair = warp >> 3;               // 0 or 1
    const int hg   = warp & 7;
    const int hloc = hg * 8 + (lane & 7);
    const int gtyp = lane >> 3;               // 0:i 1:f 2:g 3:o
    const int g    = gtyp * 64 + hloc;

    const int bl0 = 2 * pair;
    const int bg0 = blockIdx.x * BPC + bl0;

    __shared__ __align__(16) float h_s[2][BPC][Hn];

    unsigned long long whh[32];
    {
        const float* wr = W_hh + g * Hn;
#pragma unroll
        for (int k = 0; k < 32; k++) whh[k] = pack2(wr[2 * k], wr[2 * k + 1]);
    }

    // act = A * tanh(S * pre) + C :  sigmoid -> S=.5, A=.5, C=.5 ; g -> 1,1,0
    const float S = (gtyp == 2) ? 1.0f : 0.5f;
    const float A = (gtyp == 2) ? 1.0f : 0.5f;
    const float C = (gtyp == 2) ? 0.0f : 0.5f;

    float c = 0.0f;

    const size_t xstride = (size_t)(Bn / 2) * Gn;
    const float2* xwp = g_xw2
        + (size_t)(blockIdx.x * 2 + pair) * Gn + hg * 32 + lane;
    const int bsel = (lane >> 3) & 1;
    float* hallp = g_hall + (size_t)(bg0 + bsel) * Hn + hloc;

    if (tid < BPC * Hn) ((float*)h_s[0])[tid] = 0.0f;

    // depth-2 prefetch pipeline: xr = xw[t], xn = xw[t+1]
    float2 xr = xwp[0];
    float2 xn = xwp[xstride];
    xwp += 2 * xstride;
    __syncthreads();

    int buf = 0;
    for (int t = 0; t < Tn; t++) {
        // issue load for t+2 (pad rows cover t=Tn-2, Tn-1 -- values dead)
        float2 xf = *xwp;
        xwp += xstride;

        // gate pre-activation: h . W_hh (x-part + biases already in xr)
        unsigned long long a00 = 0ull, a01 = 0ull, a10 = 0ull, a11 = 0ull;
        const ulonglong2* hp0 = (const ulonglong2*)h_s[buf][bl0];
        const ulonglong2* hp1 = (const ulonglong2*)h_s[buf][bl0 + 1];
#pragma unroll
        for (int k = 0; k < 16; k++) {
            ulonglong2 h0 = hp0[k];
            ulonglong2 h1 = hp1[k];
            a00 = ffma2(h0.x, whh[2 * k],     a00);
            a01 = ffma2(h0.y, whh[2 * k + 1], a01);
            a10 = ffma2(h1.x, whh[2 * k],     a10);
            a11 = ffma2(h1.y, whh[2 * k + 1], a11);
        }
        unsigned long long s0 = add2(a00, a01);   // packed pairwise combine
        unsigned long long s1 = add2(a10, a11);
        float l0, u0, l1, u1;
        unpack2(s0, l0, u0);
        unpack2(s1, l1, u1);
        float acc0 = (xr.x + l0) + u0;
        float acc1 = (xr.y + l1) + u1;
        xr = xn;          // waits on load issued LAST step -> hidden
        xn = xf;

        float act0 = fmaf(A, tanhf_fast(S * acc0), C);
        float act1 = fmaf(A, tanhf_fast(S * acc1), C);

        // gather i,f,g,o for this lane's (h, batch)
        const int base = lane & 7;
        float i0 = __shfl_sync(0xffffffffu, act0, base);
        float i1 = __shfl_sync(0xffffffffu, act1, base);
        float f0 = __shfl_sync(0xffffffffu, act0, base + 8);
        float f1 = __shfl_sync(0xffffffffu, act1, base + 8);
        float g0 = __shfl_sync(0xffffffffu, act0, base + 16);
        float g1 = __shfl_sync(0xffffffffu, act1, base + 16);
        float o0 = __shfl_sync(0xffffffffu, act0, base + 24);
        float o1 = __shfl_sync(0xffffffffu, act1, base + 24);
        const bool sel = (lane & 8) != 0;
        float iv = sel ? i1 : i0;
        float fv = sel ? f1 : f0;
        float gv = sel ? g1 : g0;
        float ov = sel ? o1 : o0;

        // cell/hidden update: lanes 0-15 own (h = hloc, batch = bl0+bsel)
        c = fmaf(fv, c, iv * gv);
        float hv = ov * tanhf_fast(c);
        if (lane < 16) {
            h_s[buf ^ 1][bl0 + bsel][hloc] = hv;
            *hallp = hv;
        }
        hallp += (size_t)Bn * Hn;
        __syncthreads();
        buf ^= 1;
    }
}

// ============================================================================
// Stage 2 (unchanged, ~71us reproducible): single-pass BN-stats +
// masked-extrema + pool + FC, one CTA per timestep.
// ============================================================================
__global__ __launch_bounds__(256)
void bn_pool_fc_kernel(const float* __restrict__ pg,     // [T,OUT]
                       const float* __restrict__ gamma,  // [H]
                       const float* __restrict__ beta,   // [H]
                       const float* __restrict__ W_fc,   // [OUT, H+OUT]
                       const float* __restrict__ b_fc,   // [OUT]
                       const float* __restrict__ mask,   // [B,H]
                       float* __restrict__ out)          // [T,1,OUT]
{
    const int t   = blockIdx.x;
    const int tid = threadIdx.x;
    const int h   = tid & 63;
    const int grp = tid >> 6;

    const float* base = g_hall + (size_t)t * Bn * Hn;

    __shared__ float rS[4][Hn], rQ[4][Hn], rMx[4][Hn], rMn[4][Hn],
                     rMv[4][Hn], rZ[4][Hn];
    __shared__ float pooled[Hn];

    float s = 0.0f, ss = 0.0f;
    float vmx = -FLT_MAX, vmn = FLT_MAX, mv = 0.0f, anyz = 0.0f;
#pragma unroll 4
    for (int bb = grp; bb < Bn; bb += 4) {
        float v = base[bb * Hn + h];
        float m = mask[bb * Hn + h];
        s  += v;
        ss += v * v;
        if (m > 0.0f) {
            vmx = fmaxf(vmx, v);
            vmn = fminf(vmn, v);
            mv  = fmaxf(mv, m);
        } else {
            anyz = 1.0f;
        }
    }
    rS[grp][h] = s;    rQ[grp][h] = ss;
    rMx[grp][h] = vmx; rMn[grp][h] = vmn;
    rMv[grp][h] = mv;  rZ[grp][h] = anyz;
    __syncthreads();

    if (tid < Hn) {
        float sum = rS[0][tid] + rS[1][tid] + rS[2][tid] + rS[3][tid];
        float sq  = rQ[0][tid] + rQ[1][tid] + rQ[2][tid] + rQ[3][tid];
        float mx  = fmaxf(fmaxf(rMx[0][tid], rMx[1][tid]),
                          fmaxf(rMx[2][tid], rMx[3][tid]));
        float mn  = fminf(fminf(rMn[0][tid], rMn[1][tid]),
                          fminf(rMn[2][tid], rMn[3][tid]));
        float m   = fmaxf(fmaxf(rMv[0][tid], rMv[1][tid]),
                          fmaxf(rMv[2][tid], rMv[3][tid]));
        float z   = fmaxf(fmaxf(rZ[0][tid], rZ[1][tid]),
                          fmaxf(rZ[2][tid], rZ[3][tid]));
        float mean = sum * (1.0f / Bn);
        float var  = sq * (1.0f / Bn) - mean * mean;
        float rstd = rsqrtf(var + 1e-5f);
        float sc   = rstd * gamma[tid];
        float sh   = beta[tid] - mean * sc;

        float p;
        if (mx == -FLT_MAX) {
            p = 0.0f;
        } else {
            float vstar = (sc >= 0.0f) ? mx : mn;
            p = m * (vstar * sc + sh);
            if (z > 0.0f) p = fmaxf(p, 0.0f);
        }
        pooled[tid] = p;
    }
    __syncthreads();

    if (tid < OUTn) {
        const float* w = W_fc + tid * (Hn + OUTn);
        float acc = b_fc[tid];
#pragma unroll
        for (int k = 0; k < Hn; k++) acc += pooled[k] * w[k];
#pragma unroll
        for (int k = 0; k < OUTn; k++) acc += pg[t * OUTn + k] * w[Hn + k];
        out[t * OUTn + tid] = acc;
    }
}

// ============================================================================
// Launch
// ============================================================================
extern "C" void kernel_launch(void* const* d_in, const int* in_sizes, int n_in,
                              void* d_out, int out_size) {
    const float* x      = (const float*)d_in[0];
    const float* pg     = (const float*)d_in[1];
    const float* W_ih   = (const float*)d_in[2];
    const float* W_hh   = (const float*)d_in[3];
    const float* b_ih   = (const float*)d_in[4];
    const float* b_hh   = (const float*)d_in[5];
    const float* gamma  = (const float*)d_in[6];
    const float* beta   = (const float*)d_in[7];
    const float* W_fc   = (const float*)d_in[8];
    const float* b_fc   = (const float*)d_in[9];
    const float* dmask  = (const float*)d_in[10];
    float* out = (float*)d_out;

    xw_kernel<<<Tn, 256>>>(x, W_ih, b_ih, b_hh);
    lstm_kernel<<<Bn / BPC, 512>>>(W_hh);
    bn_pool_fc_kernel<<<Tn, 256>>>(pg, gamma, beta, W_fc, b_fc, dmask, out);
}